// round 1
// baseline (speedup 1.0000x reference)
#include <cuda_runtime.h>
#include <math.h>

#define NN 4096
#define DD 256
#define HH 8
#define HDIM 32
#define ROWCAP 256
#define EPS 1e-5f
#define FFD 512

// ---------------- static scratch (no allocation allowed) ----------------
__device__ int   g_cols[NN * ROWCAP];
__device__ float g_avals[NN * ROWCAP];
__device__ int   g_nnz[NN];
__device__ float g_Q[NN * DD];     // permuted [n][head*32+hd], pre-scaled
__device__ float g_K[NN * DD];     // permuted
__device__ float g_V[NN * DD];     // permuted
__device__ float g_attn[NN * DD];  // attention out, natural layout [n][d]
__device__ float g_x1[NN * DD];    // Wo proj + residual
__device__ float g_bn1[NN * DD];   // after batchnorm 1
__device__ float g_mid[NN * FFD];  // FFN hidden
__device__ float g_x2[NN * DD];    // FFN out + residual
// [0:256) vsum, [256:512) s1, [512:768) q1, [768:1024) s2, [1024:1280) q2
__device__ float g_stats[1280];

// ---------------- CSR build over A ----------------
__global__ void __launch_bounds__(256) csr_build(const float* __restrict__ A) {
    int row = blockIdx.x;
    __shared__ int cnt;
    if (threadIdx.x == 0) cnt = 0;
    __syncthreads();
    const float* Ar = A + (size_t)row * NN;
    for (int c = threadIdx.x; c < NN; c += 256) {
        float a = Ar[c];
        if (a != 0.0f) {
            int p = atomicAdd(&cnt, 1);
            if (p < ROWCAP) {
                g_cols[row * ROWCAP + p] = c;
                g_avals[row * ROWCAP + p] = a;
            }
        }
    }
    __syncthreads();
    if (threadIdx.x == 0) g_nnz[row] = (cnt < ROWCAP) ? cnt : ROWCAP;
}

// ---------------- generic SGEMM: Y[M,Nc] = X[M,K] @ W[Nc,K]^T (+epilogue) --
// mode 0: plain   mode 1: head-permute output + scale   mode 2: relu
// mode 3: add residual
#define GBM 64
#define GBN 64
#define GBK 16

__global__ void __launch_bounds__(256) gemm_wt(
    const float* __restrict__ X, const float* __restrict__ W,
    float* __restrict__ Y, int M, int K, int Nc,
    int mode, const float* __restrict__ res, float scale)
{
    __shared__ float As[GBK][GBM + 4];
    __shared__ float Bs[GBK][GBN + 4];
    int tid = threadIdx.x;
    int m0 = blockIdx.y * GBM;
    int n0 = blockIdx.x * GBN;
    int tx = tid & 15, ty = tid >> 4;
    int tm = ty * 4, tn = tx * 4;

    int lr = tid >> 2;            // 0..63
    int lc = (tid & 3) * 4;       // 0,4,8,12

    float acc[4][4] = {};

    for (int kt = 0; kt < K; kt += GBK) {
        float4 xa = *(const float4*)&X[(size_t)(m0 + lr) * K + kt + lc];
        As[lc + 0][lr] = xa.x; As[lc + 1][lr] = xa.y;
        As[lc + 2][lr] = xa.z; As[lc + 3][lr] = xa.w;
        float4 wb = *(const float4*)&W[(size_t)(n0 + lr) * K + kt + lc];
        Bs[lc + 0][lr] = wb.x; Bs[lc + 1][lr] = wb.y;
        Bs[lc + 2][lr] = wb.z; Bs[lc + 3][lr] = wb.w;
        __syncthreads();
#pragma unroll
        for (int k = 0; k < GBK; k++) {
            float4 a = *(const float4*)&As[k][tm];
            float4 b = *(const float4*)&Bs[k][tn];
            acc[0][0] += a.x * b.x; acc[0][1] += a.x * b.y;
            acc[0][2] += a.x * b.z; acc[0][3] += a.x * b.w;
            acc[1][0] += a.y * b.x; acc[1][1] += a.y * b.y;
            acc[1][2] += a.y * b.z; acc[1][3] += a.y * b.w;
            acc[2][0] += a.z * b.x; acc[2][1] += a.z * b.y;
            acc[2][2] += a.z * b.z; acc[2][3] += a.z * b.w;
            acc[3][0] += a.w * b.x; acc[3][1] += a.w * b.y;
            acc[3][2] += a.w * b.z; acc[3][3] += a.w * b.w;
        }
        __syncthreads();
    }

#pragma unroll
    for (int i = 0; i < 4; i++) {
        int m = m0 + tm + i;
#pragma unroll
        for (int j = 0; j < 4; j++) {
            int n = n0 + tn + j;
            float v = acc[i][j];
            if (mode == 1) {
                // d = hd*H + h  ->  permuted col p = h*32 + hd
                int p = (n & 7) * HDIM + (n >> 3);
                Y[(size_t)m * Nc + p] = v * scale;
            } else if (mode == 2) {
                Y[(size_t)m * Nc + n] = fmaxf(v, 0.0f);
            } else if (mode == 3) {
                Y[(size_t)m * Nc + n] = v + res[(size_t)m * Nc + n];
            } else {
                Y[(size_t)m * Nc + n] = v;
            }
        }
    }
}

// ---------------- zero the stats scratch ----------------
__global__ void zero_stats() {
    g_stats[blockIdx.x * 256 + threadIdx.x] = 0.0f;
}

// ---------------- column sum of V (permuted layout) -> g_stats[0:256) -----
__global__ void __launch_bounds__(256) colsum_v() {
    float s = 0.0f;
    int c = threadIdx.x;
    int r0 = blockIdx.x * 64;
    for (int r = r0; r < r0 + 64; r++) s += g_V[(size_t)r * DD + c];
    atomicAdd(&g_stats[c], s);
}

// ---------------- sparse masked-softmax attention ----------------
// out[n][hd*8+h] = (Vsum + sum_nz (e-1) v) / ((N-nnz) + sum_nz e)
__global__ void __launch_bounds__(256) attn_sparse(float* __restrict__ out) {
    int n = blockIdx.x;
    int w = threadIdx.x >> 5;     // head
    int lane = threadIdx.x & 31;  // hd
    int base = w * HDIM + lane;

    float q = g_Q[(size_t)n * DD + base];   // already scaled by D^-0.5
    float acc = g_stats[base];              // Vsum
    int nnz = g_nnz[n];
    float z = (float)(NN - nnz);
    const int*   cols = g_cols  + (size_t)n * ROWCAP;
    const float* av   = g_avals + (size_t)n * ROWCAP;

    for (int i = 0; i < nnz; i++) {
        int m = cols[i];
        float a = av[i];
        float s = q * g_K[(size_t)m * DD + base];
#pragma unroll
        for (int off = 16; off; off >>= 1)
            s += __shfl_xor_sync(0xffffffffu, s, off);
        float e = expf(a * s);
        z += e;
        acc += (e - 1.0f) * g_V[(size_t)m * DD + base];
    }
    // natural layout column d = hd*H + h
    out[(size_t)n * DD + lane * HH + w] = acc / z;
}

// ---------------- batchnorm stats (sum, sumsq per column) ----------------
__global__ void __launch_bounds__(256) bn_stats(
    const float* __restrict__ X, float* __restrict__ sums, float* __restrict__ sqs)
{
    float s = 0.0f, q = 0.0f;
    int c = threadIdx.x;
    int r0 = blockIdx.x * 64;
    for (int r = r0; r < r0 + 64; r++) {
        float x = X[(size_t)r * DD + c];
        s += x; q += x * x;
    }
    atomicAdd(&sums[c], s);
    atomicAdd(&sqs[c], q);
}

// ---------------- batchnorm apply ----------------
__global__ void __launch_bounds__(256) bn_apply(
    const float* __restrict__ X, const float* __restrict__ sums,
    const float* __restrict__ sqs, const float* __restrict__ g,
    const float* __restrict__ b, float* __restrict__ Y)
{
    int c = threadIdx.x;
    size_t idx = (size_t)blockIdx.x * DD + c;
    float m = sums[c] * (1.0f / NN);
    float v = sqs[c] * (1.0f / NN) - m * m;
    Y[idx] = (X[idx] - m) * rsqrtf(v + EPS) * g[c] + b[c];
}

// ---------------- launch ----------------
extern "C" void kernel_launch(void* const* d_in, const int* in_sizes, int n_in,
                              void* d_out, int out_size)
{
    const float* A  = (const float*)d_in[0];
    const float* h  = (const float*)d_in[1];
    const float* Wq = (const float*)d_in[2];
    const float* Wk = (const float*)d_in[3];
    const float* Wv = (const float*)d_in[4];
    const float* Wo = (const float*)d_in[5];
    const float* g1 = (const float*)d_in[6];
    const float* b1 = (const float*)d_in[7];
    const float* g2 = (const float*)d_in[8];
    const float* b2 = (const float*)d_in[9];
    const float* W1 = (const float*)d_in[10];
    const float* W2 = (const float*)d_in[11];
    float* out = (float*)d_out;

    float *pQ, *pK, *pV, *pAttn, *pX1, *pBN1, *pMid, *pX2, *pStats;
    cudaGetSymbolAddress((void**)&pQ,    g_Q);
    cudaGetSymbolAddress((void**)&pK,    g_K);
    cudaGetSymbolAddress((void**)&pV,    g_V);
    cudaGetSymbolAddress((void**)&pAttn, g_attn);
    cudaGetSymbolAddress((void**)&pX1,   g_x1);
    cudaGetSymbolAddress((void**)&pBN1,  g_bn1);
    cudaGetSymbolAddress((void**)&pMid,  g_mid);
    cudaGetSymbolAddress((void**)&pX2,   g_x2);
    cudaGetSymbolAddress((void**)&pStats, g_stats);

    const float SCALE = 0.0625f;  // 256^-0.5

    zero_stats<<<5, 256>>>();
    csr_build<<<NN, 256>>>(A);

    dim3 g256(DD / GBN, NN / GBM);      // (4, 64)
    dim3 g512(FFD / GBN, NN / GBM);     // (8, 64)

    gemm_wt<<<g256, 256>>>(h, Wq, pQ, NN, DD, DD, 1, nullptr, SCALE);
    gemm_wt<<<g256, 256>>>(h, Wk, pK, NN, DD, DD, 1, nullptr, 1.0f);
    gemm_wt<<<g256, 256>>>(h, Wv, pV, NN, DD, DD, 1, nullptr, 1.0f);

    colsum_v<<<64, 256>>>();
    attn_sparse<<<NN, 256>>>(pAttn);

    // out proj + residual(h)
    gemm_wt<<<g256, 256>>>(pAttn, Wo, pX1, NN, DD, DD, 3, h, 1.0f);

    bn_stats<<<64, 256>>>(pX1, pStats + 256, pStats + 512);
    bn_apply<<<NN, 256>>>(pX1, pStats + 256, pStats + 512, g1, b1, pBN1);

    // FFN
    gemm_wt<<<g512, 256>>>(pBN1, W1, pMid, NN, DD, FFD, 2, nullptr, 1.0f);
    gemm_wt<<<g256, 256>>>(pMid, W2, pX2, NN, FFD, DD, 3, pBN1, 1.0f);

    bn_stats<<<64, 256>>>(pX2, pStats + 768, pStats + 1024);
    bn_apply<<<NN, 256>>>(pX2, pStats + 768, pStats + 1024, g2, b2, out);
}

// round 2
// speedup vs baseline: 1.3458x; 1.3458x over previous
#include <cuda_runtime.h>
#include <math.h>

#define NN 4096
#define DD 256
#define HH 8
#define HDIM 32
#define ROWCAP 256
#define EPS 1e-5f
#define FFD 512

// ---------------- static scratch ----------------
__device__ int   g_cols[NN * ROWCAP];
__device__ float g_avals[NN * ROWCAP];
__device__ int   g_nnz[NN];
__device__ float g_Q[NN * DD];     // permuted [n][head*32+hd], pre-scaled
__device__ float g_K[NN * DD];
__device__ float g_V[NN * DD];
__device__ float g_attn[NN * DD];  // natural layout [n][d]
__device__ float g_x1[NN * DD];
__device__ float g_bn1[NN * DD];
__device__ float g_mid[NN * FFD];
__device__ float g_x2[NN * DD];
__device__ float g_stats[1280];

// ---------------- CSR build over A ----------------
__global__ void __launch_bounds__(256) csr_build(const float* __restrict__ A) {
    int row = blockIdx.x;
    __shared__ int cnt;
    if (threadIdx.x == 0) cnt = 0;
    __syncthreads();
    const float4* Ar = (const float4*)(A + (size_t)row * NN);
    for (int c4 = threadIdx.x; c4 < NN / 4; c4 += 256) {
        float4 a4 = Ar[c4];
        float vals[4] = {a4.x, a4.y, a4.z, a4.w};
#pragma unroll
        for (int j = 0; j < 4; j++) {
            if (vals[j] != 0.0f) {
                int p = atomicAdd(&cnt, 1);
                if (p < ROWCAP) {
                    g_cols[row * ROWCAP + p] = c4 * 4 + j;
                    g_avals[row * ROWCAP + p] = vals[j];
                }
            }
        }
    }
    __syncthreads();
    if (threadIdx.x == 0) g_nnz[row] = (cnt < ROWCAP) ? cnt : ROWCAP;
}

// ---------------- SGEMM body: Y[M,Nc] = X[M,K] @ W[Nc,K]^T ----------------
// 128x64 block tile, 8x4 micro tile, BK=16, double-buffered smem, 1 sync/tile
// mode 0: plain   1: head-permute + scale   2: relu   3: +residual
#define BM 128
#define BN 64
#define BK 16

__device__ __forceinline__ void gemm_body(
    const float* __restrict__ X, const float* __restrict__ W,
    float* __restrict__ Y, int K, int Nc,
    int mode, const float* __restrict__ res, float scale)
{
    __shared__ float As[2][BK][BM + 4];
    __shared__ float Bs[2][BK][BN + 4];
    int tid = threadIdx.x;
    int m0 = blockIdx.y * BM;
    int n0 = blockIdx.x * BN;
    int tn = (tid & 15) * 4;
    int tm = (tid >> 4) * 8;

    int lr = tid >> 2;            // 0..63
    int lc = (tid & 3) * 4;       // 0,4,8,12

    const float* Xb = X + (size_t)m0 * K + lc;
    const float* Wb = W + (size_t)n0 * K + lc;

    // preload tile 0 into registers
    float4 xa0 = *(const float4*)&Xb[(size_t)lr * K];
    float4 xa1 = *(const float4*)&Xb[(size_t)(lr + 64) * K];
    float4 wb  = *(const float4*)&Wb[(size_t)lr * K];

    float acc[8][4] = {};
    int nk = K / BK;

    for (int kt = 0; kt < nk; kt++) {
        int buf = kt & 1;
        // store current tile (transposed) into smem
        As[buf][lc + 0][lr] = xa0.x; As[buf][lc + 1][lr] = xa0.y;
        As[buf][lc + 2][lr] = xa0.z; As[buf][lc + 3][lr] = xa0.w;
        As[buf][lc + 0][lr + 64] = xa1.x; As[buf][lc + 1][lr + 64] = xa1.y;
        As[buf][lc + 2][lr + 64] = xa1.z; As[buf][lc + 3][lr + 64] = xa1.w;
        Bs[buf][lc + 0][lr] = wb.x; Bs[buf][lc + 1][lr] = wb.y;
        Bs[buf][lc + 2][lr] = wb.z; Bs[buf][lc + 3][lr] = wb.w;
        __syncthreads();
        // prefetch next tile (overlaps compute)
        if (kt + 1 < nk) {
            int off = (kt + 1) * BK;
            xa0 = *(const float4*)&Xb[(size_t)lr * K + off];
            xa1 = *(const float4*)&Xb[(size_t)(lr + 64) * K + off];
            wb  = *(const float4*)&Wb[(size_t)lr * K + off];
        }
#pragma unroll
        for (int k = 0; k < BK; k++) {
            float4 a0 = *(const float4*)&As[buf][k][tm];
            float4 a1 = *(const float4*)&As[buf][k][tm + 4];
            float4 b  = *(const float4*)&Bs[buf][k][tn];
            acc[0][0] += a0.x * b.x; acc[0][1] += a0.x * b.y; acc[0][2] += a0.x * b.z; acc[0][3] += a0.x * b.w;
            acc[1][0] += a0.y * b.x; acc[1][1] += a0.y * b.y; acc[1][2] += a0.y * b.z; acc[1][3] += a0.y * b.w;
            acc[2][0] += a0.z * b.x; acc[2][1] += a0.z * b.y; acc[2][2] += a0.z * b.z; acc[2][3] += a0.z * b.w;
            acc[3][0] += a0.w * b.x; acc[3][1] += a0.w * b.y; acc[3][2] += a0.w * b.z; acc[3][3] += a0.w * b.w;
            acc[4][0] += a1.x * b.x; acc[4][1] += a1.x * b.y; acc[4][2] += a1.x * b.z; acc[4][3] += a1.x * b.w;
            acc[5][0] += a1.y * b.x; acc[5][1] += a1.y * b.y; acc[5][2] += a1.y * b.z; acc[5][3] += a1.y * b.w;
            acc[6][0] += a1.z * b.x; acc[6][1] += a1.z * b.y; acc[6][2] += a1.z * b.z; acc[6][3] += a1.z * b.w;
            acc[7][0] += a1.w * b.x; acc[7][1] += a1.w * b.y; acc[7][2] += a1.w * b.z; acc[7][3] += a1.w * b.w;
        }
    }

#pragma unroll
    for (int i = 0; i < 8; i++) {
        int m = m0 + tm + i;
        size_t rowoff = (size_t)m * Nc;
        if (mode == 1) {
#pragma unroll
            for (int j = 0; j < 4; j++) {
                int n = n0 + tn + j;
                int p = (n & 7) * HDIM + (n >> 3);
                Y[rowoff + p] = acc[i][j] * scale;
            }
        } else if (mode == 2) {
            float4 v = make_float4(fmaxf(acc[i][0], 0.f), fmaxf(acc[i][1], 0.f),
                                   fmaxf(acc[i][2], 0.f), fmaxf(acc[i][3], 0.f));
            *(float4*)&Y[rowoff + n0 + tn] = v;
        } else if (mode == 3) {
            float4 r = *(const float4*)&res[rowoff + n0 + tn];
            float4 v = make_float4(acc[i][0] + r.x, acc[i][1] + r.y,
                                   acc[i][2] + r.z, acc[i][3] + r.w);
            *(float4*)&Y[rowoff + n0 + tn] = v;
        } else {
            float4 v = make_float4(acc[i][0], acc[i][1], acc[i][2], acc[i][3]);
            *(float4*)&Y[rowoff + n0 + tn] = v;
        }
    }
}

__global__ void __launch_bounds__(256) qkv_gemm(
    const float* __restrict__ X, const float* __restrict__ Wq,
    const float* __restrict__ Wk, const float* __restrict__ Wv)
{
    int z = blockIdx.z;
    const float* W = (z == 0) ? Wq : ((z == 1) ? Wk : Wv);
    float* Y = (z == 0) ? g_Q : ((z == 1) ? g_K : g_V);
    float scale = (z == 0) ? 0.0625f : 1.0f;
    gemm_body(X, W, Y, DD, DD, 1, nullptr, scale);
}

__global__ void __launch_bounds__(256) gemm_k(
    const float* __restrict__ X, const float* __restrict__ W,
    float* __restrict__ Y, int K, int Nc, int mode, const float* __restrict__ res)
{
    gemm_body(X, W, Y, K, Nc, mode, res, 1.0f);
}

// ---------------- small kernels ----------------
__global__ void zero_stats() { g_stats[blockIdx.x * 256 + threadIdx.x] = 0.0f; }

__global__ void __launch_bounds__(256) colsum_v() {
    float s = 0.0f;
    int c = threadIdx.x;
    int r0 = blockIdx.x * 64;
    for (int r = r0; r < r0 + 64; r++) s += g_V[(size_t)r * DD + c];
    atomicAdd(&g_stats[c], s);
}

// ---------------- sparse masked-softmax attention (2x unrolled) ----------
__global__ void __launch_bounds__(256) attn_sparse(float* __restrict__ out) {
    int n = blockIdx.x;
    int w = threadIdx.x >> 5;
    int lane = threadIdx.x & 31;
    int base = w * HDIM + lane;

    float q = g_Q[(size_t)n * DD + base];
    float acc = g_stats[base];
    int nnz = g_nnz[n];
    float z = (float)(NN - nnz);
    const int*   cols = g_cols  + (size_t)n * ROWCAP;
    const float* av   = g_avals + (size_t)n * ROWCAP;

    int i = 0;
    for (; i + 2 <= nnz; i += 2) {
        int m1 = cols[i], m2 = cols[i + 1];
        float a1 = av[i], a2 = av[i + 1];
        float k1 = g_K[(size_t)m1 * DD + base];
        float k2 = g_K[(size_t)m2 * DD + base];
        float v1 = g_V[(size_t)m1 * DD + base];
        float v2 = g_V[(size_t)m2 * DD + base];
        float s1 = q * k1, s2 = q * k2;
#pragma unroll
        for (int off = 16; off; off >>= 1) {
            s1 += __shfl_xor_sync(0xffffffffu, s1, off);
            s2 += __shfl_xor_sync(0xffffffffu, s2, off);
        }
        float e1 = __expf(a1 * s1);
        float e2 = __expf(a2 * s2);
        z += e1 + e2;
        acc += (e1 - 1.0f) * v1 + (e2 - 1.0f) * v2;
    }
    if (i < nnz) {
        int m1 = cols[i];
        float a1 = av[i];
        float s1 = q * g_K[(size_t)m1 * DD + base];
#pragma unroll
        for (int off = 16; off; off >>= 1)
            s1 += __shfl_xor_sync(0xffffffffu, s1, off);
        float e1 = __expf(a1 * s1);
        z += e1;
        acc += (e1 - 1.0f) * g_V[(size_t)m1 * DD + base];
    }
    out[(size_t)n * DD + lane * HH + w] = acc / z;
}

// ---------------- batchnorm ----------------
__global__ void __launch_bounds__(256) bn_stats(
    const float* __restrict__ X, float* __restrict__ sums, float* __restrict__ sqs)
{
    float s = 0.0f, q = 0.0f;
    int c = threadIdx.x;
    int r0 = blockIdx.x * 64;
    for (int r = r0; r < r0 + 64; r++) {
        float x = X[(size_t)r * DD + c];
        s += x; q += x * x;
    }
    atomicAdd(&sums[c], s);
    atomicAdd(&sqs[c], q);
}

__global__ void __launch_bounds__(256) bn_apply(
    const float* __restrict__ X, const float* __restrict__ sums,
    const float* __restrict__ sqs, const float* __restrict__ g,
    const float* __restrict__ b, float* __restrict__ Y)
{
    int c = threadIdx.x;
    size_t idx = (size_t)blockIdx.x * DD + c;
    float m = sums[c] * (1.0f / NN);
    float v = sqs[c] * (1.0f / NN) - m * m;
    Y[idx] = (X[idx] - m) * rsqrtf(v + EPS) * g[c] + b[c];
}

// ---------------- launch ----------------
extern "C" void kernel_launch(void* const* d_in, const int* in_sizes, int n_in,
                              void* d_out, int out_size)
{
    const float* A  = (const float*)d_in[0];
    const float* h  = (const float*)d_in[1];
    const float* Wq = (const float*)d_in[2];
    const float* Wk = (const float*)d_in[3];
    const float* Wv = (const float*)d_in[4];
    const float* Wo = (const float*)d_in[5];
    const float* g1 = (const float*)d_in[6];
    const float* b1 = (const float*)d_in[7];
    const float* g2 = (const float*)d_in[8];
    const float* b2 = (const float*)d_in[9];
    const float* W1 = (const float*)d_in[10];
    const float* W2 = (const float*)d_in[11];
    float* out = (float*)d_out;

    float *pAttn, *pX1, *pBN1, *pMid, *pX2, *pStats;
    cudaGetSymbolAddress((void**)&pAttn, g_attn);
    cudaGetSymbolAddress((void**)&pX1,   g_x1);
    cudaGetSymbolAddress((void**)&pBN1,  g_bn1);
    cudaGetSymbolAddress((void**)&pMid,  g_mid);
    cudaGetSymbolAddress((void**)&pX2,   g_x2);
    cudaGetSymbolAddress((void**)&pStats, g_stats);

    zero_stats<<<5, 256>>>();
    csr_build<<<NN, 256>>>(A);

    dim3 gQKV(DD / BN, NN / BM, 3);     // (4, 32, 3)
    dim3 g256(DD / BN, NN / BM);        // (4, 32)
    dim3 g512(FFD / BN, NN / BM);       // (8, 32)

    qkv_gemm<<<gQKV, 256>>>(h, Wq, Wk, Wv);

    colsum_v<<<64, 256>>>();
    attn_sparse<<<NN, 256>>>(pAttn);

    gemm_k<<<g256, 256>>>(pAttn, Wo, pX1, DD, DD, 3, h);

    bn_stats<<<64, 256>>>(pX1, pStats + 256, pStats + 512);
    bn_apply<<<NN, 256>>>(pX1, pStats + 256, pStats + 512, g1, b1, pBN1);

    gemm_k<<<g512, 256>>>(pBN1, W1, pMid, DD, FFD, 2, nullptr);
    gemm_k<<<g256, 256>>>(pMid, W2, pX2, FFD, DD, 3, pBN1);

    bn_stats<<<64, 256>>>(pX2, pStats + 768, pStats + 1024);
    bn_apply<<<NN, 256>>>(pX2, pStats + 768, pStats + 1024, g2, b2, out);
}